// round 9
// baseline (speedup 1.0000x reference)
#include <cuda_runtime.h>
#include <cuda_bf16.h>
#include <cstdint>

#define N_NODES 50000
#define N_EDGES 800000
#define F 128
#define SCAN_BLK 1024
#define NSCAN ((N_NODES + SCAN_BLK - 1) / SCAN_BLK)   // 49

// ---------------- scratch (static device memory) -----------------------------
__device__ unsigned g_xp[(size_t)N_NODES * F];          // packed split-bf16 x (hi lo)
__device__ unsigned g_hp[2][(size_t)N_NODES * F];       // packed hidden (ping-pong)
__device__ __nv_bfloat16 g_whi[3 * 128 * 256];          // combined [Wl|Wr] hi
__device__ __nv_bfloat16 g_wlo[3 * 128 * 256];          // combined [Wl|Wr] lo
__device__ int g_deg[N_NODES];
__device__ int g_scan[N_NODES];
__device__ int g_off[N_NODES];
__device__ int g_cursor[N_NODES];
__device__ int g_bsum[64];
__device__ int g_srcs[N_EDGES];

// ---------------- pack/unpack helpers ----------------------------------------
__device__ __forceinline__ float unpack_v(unsigned u) {
    return __uint_as_float(u << 16) + __uint_as_float(u & 0xFFFF0000u);
}
__device__ __forceinline__ unsigned pack_v(float v) {
    __nv_bfloat16 h = __float2bfloat16(v);
    unsigned hb = (unsigned)__bfloat16_as_ushort(h);
    float hf = __uint_as_float(hb << 16);
    __nv_bfloat16 l = __float2bfloat16(v - hf);
    unsigned lb = (unsigned)__bfloat16_as_ushort(l);
    return hb | (lb << 16);
}
// split fp32 -> (hi bf16 bits, lo bf16 bits)
__device__ __forceinline__ void split_bits(float v, unsigned& hb, unsigned& lb) {
    hb = (unsigned)__bfloat16_as_ushort(__float2bfloat16(v));
    float r = v - __uint_as_float(hb << 16);
    lb = (unsigned)__bfloat16_as_ushort(__float2bfloat16(r));
}

// ---------------- warp-mma helpers --------------------------------------------
__device__ __forceinline__ unsigned smem_u32(const void* p) {
    unsigned a;
    asm("{ .reg .u64 t; cvta.to.shared.u64 t, %1; cvt.u32.u64 %0, t; }" : "=r"(a) : "l"(p));
    return a;
}
__device__ __forceinline__ void ldsm_x4(unsigned* r, unsigned addr) {
    asm volatile("ldmatrix.sync.aligned.m8n8.x4.shared.b16 {%0,%1,%2,%3}, [%4];"
                 : "=r"(r[0]), "=r"(r[1]), "=r"(r[2]), "=r"(r[3]) : "r"(addr));
}
__device__ __forceinline__ void mma16816(float* c, const unsigned* a, const unsigned* b) {
    asm volatile(
        "mma.sync.aligned.m16n8k16.row.col.f32.bf16.bf16.f32 "
        "{%0,%1,%2,%3}, {%4,%5,%6,%7}, {%8,%9}, {%0,%1,%2,%3};"
        : "+f"(c[0]), "+f"(c[1]), "+f"(c[2]), "+f"(c[3])
        : "r"(a[0]), "r"(a[1]), "r"(a[2]), "r"(a[3]), "r"(b[0]), "r"(b[1]));
}

// ---------------- prep: zero deg + pack weights + pack x ------------------------
__global__ void k_prep(const float* __restrict__ x,
                       const float* Wl0, const float* Wr0,
                       const float* Wl1, const float* Wr1,
                       const float* Wl2, const float* Wr2) {
    int gid = blockIdx.x * blockDim.x + threadIdx.x;
    if (gid < N_NODES) g_deg[gid] = 0;
    if (gid < 3 * 128 * 256) {
        int L = gid / (128 * 256);
        int r = gid % (128 * 256);
        int n = r / 256;
        int k = r % 256;
        const float* Wl = (L == 0) ? Wl0 : (L == 1) ? Wl1 : Wl2;
        const float* Wr = (L == 0) ? Wr0 : (L == 1) ? Wr1 : Wr2;
        float v = (k < 128) ? Wl[n * 128 + k] : Wr[n * 128 + (k - 128)];
        unsigned hb, lb;
        split_bits(v, hb, lb);
        __nv_bfloat16_raw hr; hr.x = (unsigned short)hb;
        __nv_bfloat16_raw lr; lr.x = (unsigned short)lb;
        g_whi[gid] = __nv_bfloat16(hr);
        g_wlo[gid] = __nv_bfloat16(lr);
    }
    if (gid < N_NODES * F / 4) {
        float4 v = ((const float4*)x)[gid];
        uint4 o;
        o.x = pack_v(v.x); o.y = pack_v(v.y); o.z = pack_v(v.z); o.w = pack_v(v.w);
        ((uint4*)g_xp)[gid] = o;
    }
}

// ---------------- CSR build: vectorized hist/scatter ----------------------------
__global__ void k_hist(const int* __restrict__ edge) {
    int e4 = (blockIdx.x * blockDim.x + threadIdx.x) * 4;
    if (e4 + 3 < N_EDGES) {
        uint4 d = *(const uint4*)(edge + N_EDGES + e4);
        if (d.x < N_NODES) atomicAdd(&g_deg[d.x], 1);
        if (d.y < N_NODES) atomicAdd(&g_deg[d.y], 1);
        if (d.z < N_NODES) atomicAdd(&g_deg[d.z], 1);
        if (d.w < N_NODES) atomicAdd(&g_deg[d.w], 1);
    } else {
        for (int e = e4; e < N_EDGES; e++) {
            unsigned dst = (unsigned)edge[N_EDGES + e];
            if (dst < N_NODES) atomicAdd(&g_deg[dst], 1);
        }
    }
}

__global__ void k_scan1() {
    __shared__ int s[SCAN_BLK];
    int tid = threadIdx.x;
    int i = blockIdx.x * SCAN_BLK + tid;
    int v = (i < N_NODES) ? g_deg[i] : 0;
    s[tid] = v;
    __syncthreads();
    for (int o = 1; o < SCAN_BLK; o <<= 1) {
        int t = (tid >= o) ? s[tid - o] : 0;
        __syncthreads();
        s[tid] += t;
        __syncthreads();
    }
    if (i < N_NODES) g_scan[i] = s[tid];
    if (tid == SCAN_BLK - 1) g_bsum[blockIdx.x] = s[tid];
}

__global__ void k_scan23() {
    __shared__ int bx[64];
    int tid = threadIdx.x;
    if (tid < 64) bx[tid] = (tid < NSCAN) ? g_bsum[tid] : 0;
    __syncthreads();
    if (tid == 0) {
        int run = 0;
        for (int b = 0; b < NSCAN; b++) {
            int v = bx[b];
            bx[b] = run;
            run += v;
        }
    }
    __syncthreads();
    int i = blockIdx.x * blockDim.x + tid;
    if (i < N_NODES) {
        int off = g_scan[i] - g_deg[i] + bx[i / SCAN_BLK];
        g_off[i] = off;
        g_cursor[i] = off;
    }
}

__global__ void k_scatter(const int* __restrict__ edge) {
    int e4 = (blockIdx.x * blockDim.x + threadIdx.x) * 4;
    if (e4 + 3 < N_EDGES) {
        uint4 s = *(const uint4*)(edge + e4);
        uint4 d = *(const uint4*)(edge + N_EDGES + e4);
        if (d.x < N_NODES && s.x < N_NODES) g_srcs[atomicAdd(&g_cursor[d.x], 1)] = (int)s.x;
        if (d.y < N_NODES && s.y < N_NODES) g_srcs[atomicAdd(&g_cursor[d.y], 1)] = (int)s.y;
        if (d.z < N_NODES && s.z < N_NODES) g_srcs[atomicAdd(&g_cursor[d.z], 1)] = (int)s.z;
        if (d.w < N_NODES && s.w < N_NODES) g_srcs[atomicAdd(&g_cursor[d.w], 1)] = (int)s.w;
    } else {
        for (int e = e4; e < N_EDGES; e++) {
            unsigned src = (unsigned)edge[e];
            unsigned dst = (unsigned)edge[N_EDGES + e];
            if (dst < N_NODES && src < N_NODES)
                g_srcs[atomicAdd(&g_cursor[dst], 1)] = (int)src;
        }
    }
}

// ---------------- fused layer: agg (in-smem mean) + HMMA GEMM [+ final] ---------
#define FSM_BIAS 0                         // 512 B
#define FSM_WF   512                       // 512 B
#define FSM_OUT  1024                      // 512 B
#define FSM_MH0  2048                      // mean hi, cols 0-63   (16 KB)
#define FSM_ML0  (FSM_MH0 + 16384)
#define FSM_MH1  (FSM_ML0 + 16384)         // mean hi, cols 64-127
#define FSM_ML1  (FSM_MH1 + 16384)
#define FSM_AHI  (FSM_ML1 + 16384)
#define FSM_ALO  (FSM_AHI + 16384)
#define FSM_WHI  (FSM_ALO + 16384)
#define FSM_WLO  (FSM_WHI + 16384)
#define FSM_TOTAL (FSM_WLO + 16384)        // 133120 B

__device__ __forceinline__ unsigned swoff(int row, int k) {
    return (unsigned)(row * 128 + ((((k >> 3) ^ row) & 7) << 4) + (k & 7) * 2);
}

__global__ void __launch_bounds__(256, 1) k_layer(
    const unsigned* __restrict__ Ah,          // prev hidden, packed (also agg src)
    const __nv_bfloat16* __restrict__ Whi,
    const __nv_bfloat16* __restrict__ Wlo,
    const float* __restrict__ bl,
    unsigned* __restrict__ outp,              // next hidden, packed (unused if last)
    const float* __restrict__ Wf,
    const float* __restrict__ bf,
    float* __restrict__ out,
    int last)
{
    extern __shared__ __align__(16) char smem[];
    unsigned sb = smem_u32(smem);
    int tid = threadIdx.x;
    int wid = tid >> 5;
    int lane = tid & 31;
    int wm = wid & 1;
    int wn = wid >> 1;
    int m0 = blockIdx.x * 128;

    if (tid < 128) {
        *(float*)(smem + FSM_BIAS + tid * 4) = bl[tid];
        if (last) {
            *(float*)(smem + FSM_WF + tid * 4) = Wf[tid];
            *(float*)(smem + FSM_OUT + tid * 4) = 0.f;
        }
    }

    // -------- phase A: aggregate this CTA's 128 rows into smem mean planes -----
    {
        char* MH = smem + ((lane < 16) ? FSM_MH0 : FSM_MH1);
        char* ML = smem + ((lane < 16) ? FSM_ML0 : FSM_ML1);
        int cl = (lane * 4) & 63;      // chunk-local column
        for (int i = 0; i < 16; i++) {
            int r = wid * 16 + i;
            int gr = m0 + r;
            int d = 0, o = 0;
            if (gr < N_NODES) { d = g_deg[gr]; o = g_off[gr]; }
            float a0 = 0.f, a1 = 0.f, a2 = 0.f, a3 = 0.f;
            int e = 0;
            for (; e + 4 <= d; e += 4) {
                int s0 = g_srcs[o + e];
                int s1 = g_srcs[o + e + 1];
                int s2 = g_srcs[o + e + 2];
                int s3 = g_srcs[o + e + 3];
                uint4 p0 = ((const uint4*)(Ah + (size_t)s0 * F))[lane];
                uint4 p1 = ((const uint4*)(Ah + (size_t)s1 * F))[lane];
                uint4 p2 = ((const uint4*)(Ah + (size_t)s2 * F))[lane];
                uint4 p3 = ((const uint4*)(Ah + (size_t)s3 * F))[lane];
                a0 += unpack_v(p0.x) + unpack_v(p1.x) + unpack_v(p2.x) + unpack_v(p3.x);
                a1 += unpack_v(p0.y) + unpack_v(p1.y) + unpack_v(p2.y) + unpack_v(p3.y);
                a2 += unpack_v(p0.z) + unpack_v(p1.z) + unpack_v(p2.z) + unpack_v(p3.z);
                a3 += unpack_v(p0.w) + unpack_v(p1.w) + unpack_v(p2.w) + unpack_v(p3.w);
            }
            for (; e < d; e++) {
                int s = g_srcs[o + e];
                uint4 p = ((const uint4*)(Ah + (size_t)s * F))[lane];
                a0 += unpack_v(p.x); a1 += unpack_v(p.y);
                a2 += unpack_v(p.z); a3 += unpack_v(p.w);
            }
            float inv = (d > 0) ? 1.0f / (float)d : 0.0f;
            a0 *= inv; a1 *= inv; a2 *= inv; a3 *= inv;
            unsigned h0b, l0b, h1b, l1b, h2b, l2b, h3b, l3b;
            split_bits(a0, h0b, l0b); split_bits(a1, h1b, l1b);
            split_bits(a2, h2b, l2b); split_bits(a3, h3b, l3b);
            uint2 hv = make_uint2(h0b | (h1b << 16), h2b | (h3b << 16));
            uint2 lv = make_uint2(l0b | (l1b << 16), l2b | (l3b << 16));
            unsigned off = swoff(r, cl);
            *(uint2*)(MH + off) = hv;
            *(uint2*)(ML + off) = lv;
        }
    }
    __syncthreads();

    // -------- phase B: GEMM over K=256 (chunks 0,1 = smem mean; 2,3 = h) -------
    float acc[4][4][4];
#pragma unroll
    for (int a = 0; a < 4; a++)
#pragma unroll
        for (int b = 0; b < 4; b++)
#pragma unroll
            for (int c = 0; c < 4; c++) acc[a][b][c] = 0.f;

    for (int chunk = 0; chunk < 4; chunk++) {
        int kcA = (chunk & 1) * 64;
        int kcW = chunk * 64;
        __syncthreads();
        if (chunk >= 2) {
            for (int i = tid; i < 2048; i += 256) {
                int row = i >> 4;
                int k4 = (i & 15) * 4;
                uint4 p = make_uint4(0, 0, 0, 0);
                if (m0 + row < N_NODES)
                    p = *(const uint4*)(Ah + (size_t)(m0 + row) * F + kcA + k4);
                uint2 h, l;
                h.x = (p.x & 0xFFFFu) | (p.y << 16);
                h.y = (p.z & 0xFFFFu) | (p.w << 16);
                l.x = (p.x >> 16) | (p.y & 0xFFFF0000u);
                l.y = (p.z >> 16) | (p.w & 0xFFFF0000u);
                unsigned off = swoff(row, k4);
                *(uint2*)(smem + FSM_AHI + off) = h;
                *(uint2*)(smem + FSM_ALO + off) = l;
            }
        }
        for (int i = tid; i < 1024; i += 256) {
            int n = i >> 3;
            int k8 = (i & 7) * 8;
            unsigned off = swoff(n, k8);
            *(uint4*)(smem + FSM_WHI + off) = *(const uint4*)(Whi + n * 256 + kcW + k8);
            *(uint4*)(smem + FSM_WLO + off) = *(const uint4*)(Wlo + n * 256 + kcW + k8);
        }
        __syncthreads();

        unsigned aBaseHi = sb + ((chunk == 0) ? FSM_MH0 : (chunk == 1) ? FSM_MH1 : FSM_AHI);
        unsigned aBaseLo = sb + ((chunk == 0) ? FSM_ML0 : (chunk == 1) ? FSM_ML1 : FSM_ALO);

#pragma unroll
        for (int ks = 0; ks < 4; ks++) {
            int kl = ks * 16;
            unsigned ahi[16], alo[16];
            int mrl = ((lane >> 3) & 1) * 8 + (lane & 7);
            int kkA = kl + (lane >> 4) * 8;
#pragma unroll
            for (int mf = 0; mf < 4; mf++) {
                int mrow = wm * 64 + mf * 16 + mrl;
                unsigned offA = (unsigned)(mrow * 128 + ((((kkA >> 3) ^ mrow) & 7) << 4));
                ldsm_x4(&ahi[mf * 4], aBaseHi + offA);
                ldsm_x4(&alo[mf * 4], aBaseLo + offA);
            }
            unsigned bhi[8], blo[8];
            int nrl = (lane >> 4) * 8 + (lane & 7);
            int kkB = kl + ((lane >> 3) & 1) * 8;
#pragma unroll
            for (int nf2 = 0; nf2 < 2; nf2++) {
                int nrow = wn * 32 + nf2 * 16 + nrl;
                unsigned offB = (unsigned)(nrow * 128 + ((((kkB >> 3) ^ nrow) & 7) << 4));
                ldsm_x4(&bhi[nf2 * 4], sb + FSM_WHI + offB);
                ldsm_x4(&blo[nf2 * 4], sb + FSM_WLO + offB);
            }
#pragma unroll
            for (int mf = 0; mf < 4; mf++)
#pragma unroll
                for (int nf = 0; nf < 4; nf++) {
                    const unsigned* bh = &bhi[(nf >> 1) * 4 + (nf & 1) * 2];
                    const unsigned* blp = &blo[(nf >> 1) * 4 + (nf & 1) * 2];
                    mma16816(acc[mf][nf], &ahi[mf * 4], bh);
                    mma16816(acc[mf][nf], &ahi[mf * 4], blp);
                    mma16816(acc[mf][nf], &alo[mf * 4], bh);
                }
        }
    }

    // -------- epilogue ----------------------------------------------------------
    const float* bias = (const float*)(smem + FSM_BIAS);
    if (!last) {
#pragma unroll
        for (int mf = 0; mf < 4; mf++) {
            int ra = m0 + wm * 64 + mf * 16 + (lane >> 2);
            int rb = ra + 8;
#pragma unroll
            for (int nf = 0; nf < 4; nf++) {
                int col = wn * 32 + nf * 8 + (lane & 3) * 2;
                float b0 = bias[col], b1 = bias[col + 1];
                if (ra < N_NODES) {
                    float v0 = fmaxf(acc[mf][nf][0] + b0, 0.f);
                    float v1 = fmaxf(acc[mf][nf][1] + b1, 0.f);
                    *(uint2*)(outp + (size_t)ra * F + col) = make_uint2(pack_v(v0), pack_v(v1));
                }
                if (rb < N_NODES) {
                    float v2 = fmaxf(acc[mf][nf][2] + b0, 0.f);
                    float v3 = fmaxf(acc[mf][nf][3] + b1, 0.f);
                    *(uint2*)(outp + (size_t)rb * F + col) = make_uint2(pack_v(v2), pack_v(v3));
                }
            }
        }
    } else {
        // fused final linear: out[row] = sum_col relu(gemm+bias)[col] * Wf[col] + bf
        float* sout = (float*)(smem + FSM_OUT);
        const float* wf = (const float*)(smem + FSM_WF);
#pragma unroll
        for (int mf = 0; mf < 4; mf++) {
            int la = wm * 64 + mf * 16 + (lane >> 2);
            float pa = 0.f, pb = 0.f;
#pragma unroll
            for (int nf = 0; nf < 4; nf++) {
                int col = wn * 32 + nf * 8 + (lane & 3) * 2;
                float b0 = bias[col], b1 = bias[col + 1];
                float w0 = wf[col], w1 = wf[col + 1];
                pa += fmaxf(acc[mf][nf][0] + b0, 0.f) * w0 + fmaxf(acc[mf][nf][1] + b1, 0.f) * w1;
                pb += fmaxf(acc[mf][nf][2] + b0, 0.f) * w0 + fmaxf(acc[mf][nf][3] + b1, 0.f) * w1;
            }
            pa += __shfl_xor_sync(0xFFFFFFFFu, pa, 1);
            pa += __shfl_xor_sync(0xFFFFFFFFu, pa, 2);
            pb += __shfl_xor_sync(0xFFFFFFFFu, pb, 1);
            pb += __shfl_xor_sync(0xFFFFFFFFu, pb, 2);
            if ((lane & 3) == 0) {
                atomicAdd(&sout[la], pa);
                atomicAdd(&sout[la + 8], pb);
            }
        }
        __syncthreads();
        if (tid < 128 && m0 + tid < N_NODES)
            out[m0 + tid] = sout[tid] + bf[0];
    }
}

// ---------------- launch ------------------------------------------------------------
extern "C" void kernel_launch(void* const* d_in, const int* in_sizes, int n_in,
                              void* d_out, int out_size)
{
    const float* x    = (const float*)d_in[0];
    const int*   edge = (const int*)d_in[1];   // int32 (JAX x64 disabled)
    const float* Wl[3] = {(const float*)d_in[2], (const float*)d_in[5], (const float*)d_in[8]};
    const float* bl[3] = {(const float*)d_in[3], (const float*)d_in[6], (const float*)d_in[9]};
    const float* Wr[3] = {(const float*)d_in[4], (const float*)d_in[7], (const float*)d_in[10]};
    const float* Wf = (const float*)d_in[11];
    const float* bf = (const float*)d_in[12];
    float* out = (float*)d_out;

    cudaFuncSetAttribute(k_layer, cudaFuncAttributeMaxDynamicSharedMemorySize, FSM_TOTAL);

    void* p = nullptr;
    cudaGetSymbolAddress(&p, g_xp);
    unsigned* xp = (unsigned*)p;
    cudaGetSymbolAddress(&p, g_hp);
    unsigned* h0 = (unsigned*)p;
    unsigned* h1 = h0 + (size_t)N_NODES * F;
    cudaGetSymbolAddress(&p, g_whi);
    __nv_bfloat16* whi = (__nv_bfloat16*)p;
    cudaGetSymbolAddress(&p, g_wlo);
    __nv_bfloat16* wlo = (__nv_bfloat16*)p;

    // prep (zero deg + pack W + pack x), then CSR build
    k_prep<<<(N_NODES * F / 4 + 255) / 256, 256>>>(x, Wl[0], Wr[0], Wl[1], Wr[1], Wl[2], Wr[2]);
    k_hist<<<(N_EDGES / 4 + 255) / 256, 256>>>(edge);
    k_scan1<<<NSCAN, SCAN_BLK>>>();
    k_scan23<<<(N_NODES + 255) / 256, 256>>>();
    k_scatter<<<(N_EDGES / 4 + 255) / 256, 256>>>(edge);

    const int GEMM_BLOCKS = (N_NODES + 127) / 128;   // 391

    // fused layers
    k_layer<<<GEMM_BLOCKS, 256, FSM_TOTAL>>>(xp, whi, wlo, bl[0], h0, Wf, bf, out, 0);
    k_layer<<<GEMM_BLOCKS, 256, FSM_TOTAL>>>(h0, whi + 128 * 256, wlo + 128 * 256, bl[1], h1, Wf, bf, out, 0);
    k_layer<<<GEMM_BLOCKS, 256, FSM_TOTAL>>>(h1, whi + 2 * 128 * 256, wlo + 2 * 128 * 256, bl[2], nullptr, Wf, bf, out, 1);
}

// round 10
// speedup vs baseline: 1.4899x; 1.4899x over previous
#include <cuda_runtime.h>
#include <cuda_bf16.h>
#include <cstdint>

#define N_NODES 50000
#define N_EDGES 800000
#define F 128
#define NBLK_SCAN 196        // ceil(50000/256)

// ---------------- scratch (static device memory) -----------------------------
__device__ unsigned g_xp[(size_t)N_NODES * F];          // packed split-bf16 x (hi lo)
__device__ unsigned g_hp[2][(size_t)N_NODES * F];       // packed hidden (ping-pong)
__device__ unsigned g_meanp[(size_t)N_NODES * F];       // packed mean
__device__ __nv_bfloat16 g_whi[3 * 128 * 256];          // combined [Wl|Wr] hi
__device__ __nv_bfloat16 g_wlo[3 * 128 * 256];          // combined [Wl|Wr] lo
__device__ int g_deg[N_NODES];                          // zero-init; re-zeroed by k_final
__device__ int g_off[N_NODES];
__device__ int g_cursor[N_NODES];
__device__ int g_srcs[N_EDGES];
__device__ int g_blockagg[NBLK_SCAN];
__device__ int g_blockpref[NBLK_SCAN];
__device__ int g_aggdone;
__device__ int g_prefflag;

// ---------------- pack/unpack helpers ----------------------------------------
__device__ __forceinline__ float unpack_v(unsigned u) {
    return __uint_as_float(u << 16) + __uint_as_float(u & 0xFFFF0000u);
}
__device__ __forceinline__ unsigned pack_v(float v) {
    __nv_bfloat16 h = __float2bfloat16(v);
    unsigned hb = (unsigned)__bfloat16_as_ushort(h);
    float hf = __uint_as_float(hb << 16);
    __nv_bfloat16 l = __float2bfloat16(v - hf);
    unsigned lb = (unsigned)__bfloat16_as_ushort(l);
    return hb | (lb << 16);
}

// ---------------- warp-mma helpers --------------------------------------------
__device__ __forceinline__ unsigned smem_u32(const void* p) {
    unsigned a;
    asm("{ .reg .u64 t; cvta.to.shared.u64 t, %1; cvt.u32.u64 %0, t; }" : "=r"(a) : "l"(p));
    return a;
}
__device__ __forceinline__ void ldsm_x4(unsigned* r, unsigned addr) {
    asm volatile("ldmatrix.sync.aligned.m8n8.x4.shared.b16 {%0,%1,%2,%3}, [%4];"
                 : "=r"(r[0]), "=r"(r[1]), "=r"(r[2]), "=r"(r[3]) : "r"(addr));
}
__device__ __forceinline__ void mma16816(float* c, const unsigned* a, const unsigned* b) {
    asm volatile(
        "mma.sync.aligned.m16n8k16.row.col.f32.bf16.bf16.f32 "
        "{%0,%1,%2,%3}, {%4,%5,%6,%7}, {%8,%9}, {%0,%1,%2,%3};"
        : "+f"(c[0]), "+f"(c[1]), "+f"(c[2]), "+f"(c[3])
        : "r"(a[0]), "r"(a[1]), "r"(a[2]), "r"(a[3]), "r"(b[0]), "r"(b[1]));
}

// ---------------- launch 0: prep (pack W + pack x + hist + flag reset) ----------
// deg was zeroed by the previous call's k_final (zero-init at module load for call 1)
__global__ void k_prep(const float* __restrict__ x,
                       const int* __restrict__ edge,
                       const float* Wl0, const float* Wr0,
                       const float* Wl1, const float* Wr1,
                       const float* Wl2, const float* Wr2) {
    int gid = blockIdx.x * blockDim.x + threadIdx.x;
    if (gid == 0) { g_aggdone = 0; g_prefflag = 0; }
    // histogram: 200000 threads x 4 edges
    if (gid < N_EDGES / 4) {
        uint4 d = *(const uint4*)(edge + N_EDGES + gid * 4);
        if (d.x < N_NODES) atomicAdd(&g_deg[d.x], 1);
        if (d.y < N_NODES) atomicAdd(&g_deg[d.y], 1);
        if (d.z < N_NODES) atomicAdd(&g_deg[d.z], 1);
        if (d.w < N_NODES) atomicAdd(&g_deg[d.w], 1);
    }
    // pack weights
    if (gid < 3 * 128 * 256) {
        int L = gid / (128 * 256);
        int r = gid % (128 * 256);
        int n = r / 256;
        int k = r % 256;
        const float* Wl = (L == 0) ? Wl0 : (L == 1) ? Wl1 : Wl2;
        const float* Wr = (L == 0) ? Wr0 : (L == 1) ? Wr1 : Wr2;
        float v = (k < 128) ? Wl[n * 128 + k] : Wr[n * 128 + (k - 128)];
        unsigned p = pack_v(v);
        __nv_bfloat16_raw hr; hr.x = (unsigned short)(p & 0xFFFF);
        __nv_bfloat16_raw lr; lr.x = (unsigned short)(p >> 16);
        g_whi[gid] = __nv_bfloat16(hr);
        g_wlo[gid] = __nv_bfloat16(lr);
    }
    // pack x
    if (gid < N_NODES * F / 4) {
        float4 v = ((const float4*)x)[gid];
        uint4 o;
        o.x = pack_v(v.x); o.y = pack_v(v.y); o.z = pack_v(v.z); o.w = pack_v(v.w);
        ((uint4*)g_xp)[gid] = o;
    }
}

// ---------------- launch 1: single-kernel exclusive scan of deg -----------------
__global__ void __launch_bounds__(256, 8) k_scan() {
    __shared__ int s[256];
    __shared__ int ag[256];
    __shared__ int is_last;
    int b = blockIdx.x, t = threadIdx.x;
    int i = b * 256 + t;
    int v = (i < N_NODES) ? g_deg[i] : 0;
    s[t] = v;
    __syncthreads();
    for (int o = 1; o < 256; o <<= 1) {
        int x = (t >= o) ? s[t - o] : 0;
        __syncthreads();
        s[t] += x;
        __syncthreads();
    }
    if (t == 255) {
        g_blockagg[b] = s[255];
        __threadfence();
        is_last = (atomicAdd(&g_aggdone, 1) == NBLK_SCAN - 1);
    }
    __syncthreads();
    if (is_last) {
        int a = (t < NBLK_SCAN) ? ((volatile int*)g_blockagg)[t] : 0;
        ag[t] = a;
        __syncthreads();
        for (int o = 1; o < 256; o <<= 1) {
            int x = (t >= o) ? ag[t - o] : 0;
            __syncthreads();
            ag[t] += x;
            __syncthreads();
        }
        if (t < NBLK_SCAN) g_blockpref[t] = ag[t] - a;   // exclusive
        __threadfence();
        if (t == 0) atomicExch(&g_prefflag, 1);
    }
    if (t == 0) {
        while (((volatile int*)&g_prefflag)[0] == 0) { }
    }
    __syncthreads();
    int pref = ((volatile int*)g_blockpref)[b];
    if (i < N_NODES) {
        int off = pref + s[t] - v;
        g_off[i] = off;
        g_cursor[i] = off;
    }
}

// ---------------- launch 2: scatter ---------------------------------------------
__global__ void k_scatter(const int* __restrict__ edge) {
    int e4 = (blockIdx.x * blockDim.x + threadIdx.x) * 4;
    if (e4 + 3 < N_EDGES) {
        uint4 s = *(const uint4*)(edge + e4);
        uint4 d = *(const uint4*)(edge + N_EDGES + e4);
        if (d.x < N_NODES && s.x < N_NODES) g_srcs[atomicAdd(&g_cursor[d.x], 1)] = (int)s.x;
        if (d.y < N_NODES && s.y < N_NODES) g_srcs[atomicAdd(&g_cursor[d.y], 1)] = (int)s.y;
        if (d.z < N_NODES && s.z < N_NODES) g_srcs[atomicAdd(&g_cursor[d.z], 1)] = (int)s.z;
        if (d.w < N_NODES && s.w < N_NODES) g_srcs[atomicAdd(&g_cursor[d.w], 1)] = (int)s.w;
    } else {
        for (int e = e4; e < N_EDGES; e++) {
            unsigned src = (unsigned)edge[e];
            unsigned dst = (unsigned)edge[N_EDGES + e];
            if (dst < N_NODES && src < N_NODES)
                g_srcs[atomicAdd(&g_cursor[dst], 1)] = (int)src;
        }
    }
}

// ---------------- aggregation: one warp per node (R8/R4 exact) ------------------
__global__ void k_agg(const unsigned* __restrict__ in) {
    int node = (blockIdx.x * blockDim.x + threadIdx.x) >> 5;
    if (node >= N_NODES) return;
    int lane = threadIdx.x & 31;
    int d = g_deg[node];
    int o = g_off[node];
    float a0 = 0.f, a1 = 0.f, a2 = 0.f, a3 = 0.f;
    for (int e = 0; e < d; e++) {
        int s = g_srcs[o + e];
        uint4 p = ((const uint4*)(in + (size_t)s * F))[lane];
        a0 += unpack_v(p.x); a1 += unpack_v(p.y);
        a2 += unpack_v(p.z); a3 += unpack_v(p.w);
    }
    float inv = (d > 0) ? 1.0f / (float)d : 0.0f;
    uint4 outp;
    outp.x = pack_v(a0 * inv); outp.y = pack_v(a1 * inv);
    outp.z = pack_v(a2 * inv); outp.w = pack_v(a3 * inv);
    ((uint4*)(g_meanp + (size_t)node * F))[lane] = outp;
}

// ---------------- HMMA GEMM (R8/R4 exact) ----------------------------------------
#define SM_BIAS 0
#define SM_AHI  512
#define SM_ALO  (SM_AHI + 16384)
#define SM_WHI  (SM_ALO + 16384)
#define SM_WLO  (SM_WHI + 16384)
#define SM_TOTAL (SM_WLO + 16384)     // 66048 bytes

__device__ __forceinline__ unsigned swoff(int row, int k) {
    return (unsigned)(row * 128 + ((((k >> 3) ^ row) & 7) << 4) + (k & 7) * 2);
}

__global__ void __launch_bounds__(256, 1) k_gemm(
    const unsigned* __restrict__ Am,
    const unsigned* __restrict__ Ah,
    const __nv_bfloat16* __restrict__ Whi,
    const __nv_bfloat16* __restrict__ Wlo,
    const float* __restrict__ bl,
    unsigned* __restrict__ outp)
{
    extern __shared__ __align__(16) char smem[];
    unsigned sb = smem_u32(smem);
    int tid = threadIdx.x;
    int wid = tid >> 5;
    int lane = tid & 31;
    int wm = wid & 1;
    int wn = wid >> 1;
    int m0 = blockIdx.x * 128;

    if (tid < 128) *(float*)(smem + SM_BIAS + tid * 4) = bl[tid];

    float acc[4][4][4];
#pragma unroll
    for (int a = 0; a < 4; a++)
#pragma unroll
        for (int b = 0; b < 4; b++)
#pragma unroll
            for (int c = 0; c < 4; c++) acc[a][b][c] = 0.f;

    for (int chunk = 0; chunk < 4; chunk++) {
        const unsigned* ap = (chunk < 2) ? Am : Ah;
        int kcA = (chunk & 1) * 64;
        int kcW = chunk * 64;
        __syncthreads();
        for (int i = tid; i < 2048; i += 256) {
            int row = i >> 4;
            int k4 = (i & 15) * 4;
            uint4 p = make_uint4(0, 0, 0, 0);
            if (m0 + row < N_NODES)
                p = *(const uint4*)(ap + (size_t)(m0 + row) * F + kcA + k4);
            uint2 h, l;
            h.x = (p.x & 0xFFFFu) | (p.y << 16);
            h.y = (p.z & 0xFFFFu) | (p.w << 16);
            l.x = (p.x >> 16) | (p.y & 0xFFFF0000u);
            l.y = (p.z >> 16) | (p.w & 0xFFFF0000u);
            unsigned off = swoff(row, k4);
            *(uint2*)(smem + SM_AHI + off) = h;
            *(uint2*)(smem + SM_ALO + off) = l;
        }
        for (int i = tid; i < 1024; i += 256) {
            int n = i >> 3;
            int k8 = (i & 7) * 8;
            unsigned off = swoff(n, k8);
            *(uint4*)(smem + SM_WHI + off) = *(const uint4*)(Whi + n * 256 + kcW + k8);
            *(uint4*)(smem + SM_WLO + off) = *(const uint4*)(Wlo + n * 256 + kcW + k8);
        }
        __syncthreads();

#pragma unroll
        for (int ks = 0; ks < 4; ks++) {
            int kl = ks * 16;
            unsigned ahi[16], alo[16];
            int mrl = ((lane >> 3) & 1) * 8 + (lane & 7);
            int kkA = kl + (lane >> 4) * 8;
#pragma unroll
            for (int mf = 0; mf < 4; mf++) {
                int mrow = wm * 64 + mf * 16 + mrl;
                unsigned offA = (unsigned)(mrow * 128 + ((((kkA >> 3) ^ mrow) & 7) << 4));
                ldsm_x4(&ahi[mf * 4], sb + SM_AHI + offA);
                ldsm_x4(&alo[mf * 4], sb + SM_ALO + offA);
            }
            unsigned bhi[8], blo[8];
            int nrl = (lane >> 4) * 8 + (lane & 7);
            int kkB = kl + ((lane >> 3) & 1) * 8;
#pragma unroll
            for (int nf2 = 0; nf2 < 2; nf2++) {
                int nrow = wn * 32 + nf2 * 16 + nrl;
                unsigned offB = (unsigned)(nrow * 128 + ((((kkB >> 3) ^ nrow) & 7) << 4));
                ldsm_x4(&bhi[nf2 * 4], sb + SM_WHI + offB);
                ldsm_x4(&blo[nf2 * 4], sb + SM_WLO + offB);
            }
#pragma unroll
            for (int mf = 0; mf < 4; mf++)
#pragma unroll
                for (int nf = 0; nf < 4; nf++) {
                    const unsigned* bh = &bhi[(nf >> 1) * 4 + (nf & 1) * 2];
                    const unsigned* blp = &blo[(nf >> 1) * 4 + (nf & 1) * 2];
                    mma16816(acc[mf][nf], &ahi[mf * 4], bh);
                    mma16816(acc[mf][nf], &ahi[mf * 4], blp);
                    mma16816(acc[mf][nf], &alo[mf * 4], bh);
                }
        }
    }

    const float* bias = (const float*)(smem + SM_BIAS);
#pragma unroll
    for (int mf = 0; mf < 4; mf++) {
        int ra = m0 + wm * 64 + mf * 16 + (lane >> 2);
        int rb = ra + 8;
#pragma unroll
        for (int nf = 0; nf < 4; nf++) {
            int col = wn * 32 + nf * 8 + (lane & 3) * 2;
            float b0 = bias[col], b1 = bias[col + 1];
            if (ra < N_NODES) {
                float v0 = fmaxf(acc[mf][nf][0] + b0, 0.f);
                float v1 = fmaxf(acc[mf][nf][1] + b1, 0.f);
                *(uint2*)(outp + (size_t)ra * F + col) = make_uint2(pack_v(v0), pack_v(v1));
            }
            if (rb < N_NODES) {
                float v2 = fmaxf(acc[mf][nf][2] + b0, 0.f);
                float v3 = fmaxf(acc[mf][nf][3] + b1, 0.f);
                *(uint2*)(outp + (size_t)rb * F + col) = make_uint2(pack_v(v2), pack_v(v3));
            }
        }
    }
}

// ---------------- final linear + deg re-zero for next call ----------------------
__global__ void k_final(const unsigned* __restrict__ h,
                        const float* __restrict__ Wf,
                        const float* __restrict__ bf,
                        float* __restrict__ out)
{
    int gid = blockIdx.x * blockDim.x + threadIdx.x;
    if (gid < N_NODES) g_deg[gid] = 0;        // prep for next call's histogram
    int node = gid >> 5;
    if (node >= N_NODES) return;
    int lane = gid & 31;
    uint4 p = ((const uint4*)(h + (size_t)node * F))[lane];
    float4 wv = ((const float4*)Wf)[lane];
    float s = unpack_v(p.x) * wv.x + unpack_v(p.y) * wv.y +
              unpack_v(p.z) * wv.z + unpack_v(p.w) * wv.w;
#pragma unroll
    for (int o = 16; o > 0; o >>= 1) s += __shfl_down_sync(0xFFFFFFFFu, s, o);
    if (lane == 0) out[node] = s + bf[0];
}

// ---------------- launch ------------------------------------------------------------
extern "C" void kernel_launch(void* const* d_in, const int* in_sizes, int n_in,
                              void* d_out, int out_size)
{
    const float* x    = (const float*)d_in[0];
    const int*   edge = (const int*)d_in[1];   // int32 (JAX x64 disabled)
    const float* Wl[3] = {(const float*)d_in[2], (const float*)d_in[5], (const float*)d_in[8]};
    const float* bl[3] = {(const float*)d_in[3], (const float*)d_in[6], (const float*)d_in[9]};
    const float* Wr[3] = {(const float*)d_in[4], (const float*)d_in[7], (const float*)d_in[10]};
    const float* Wf = (const float*)d_in[11];
    const float* bf = (const float*)d_in[12];
    float* out = (float*)d_out;

    cudaFuncSetAttribute(k_gemm, cudaFuncAttributeMaxDynamicSharedMemorySize, SM_TOTAL);

    void* p = nullptr;
    cudaGetSymbolAddress(&p, g_xp);
    unsigned* xp = (unsigned*)p;
    cudaGetSymbolAddress(&p, g_hp);
    unsigned* h0 = (unsigned*)p;
    unsigned* h1 = h0 + (size_t)N_NODES * F;
    cudaGetSymbolAddress(&p, g_meanp);
    unsigned* mp = (unsigned*)p;
    cudaGetSymbolAddress(&p, g_whi);
    __nv_bfloat16* whi = (__nv_bfloat16*)p;
    cudaGetSymbolAddress(&p, g_wlo);
    __nv_bfloat16* wlo = (__nv_bfloat16*)p;

    const int AGG_BLOCKS = (N_NODES * 32 + 255) / 256;
    const int GEMM_BLOCKS = (N_NODES + 127) / 128;   // 391

    // 0: prep (pack W + pack x + histogram + flag reset)
    k_prep<<<(N_NODES * F / 4 + 255) / 256, 256>>>(x, edge, Wl[0], Wr[0], Wl[1], Wr[1], Wl[2], Wr[2]);
    // 1: single-kernel scan  2: scatter
    k_scan<<<NBLK_SCAN, 256>>>();
    k_scatter<<<(N_EDGES / 4 + 255) / 256, 256>>>(edge);

    // 3: agg0 (ncu capture slot)  4: gemm0
    k_agg<<<AGG_BLOCKS, 256>>>(xp);
    k_gemm<<<GEMM_BLOCKS, 256, SM_TOTAL>>>(mp, xp, whi, wlo, bl[0], h0);
    // 5,6: layer 1
    k_agg<<<AGG_BLOCKS, 256>>>(h0);
    k_gemm<<<GEMM_BLOCKS, 256, SM_TOTAL>>>(mp, h0, whi + 128 * 256, wlo + 128 * 256, bl[1], h1);
    // 7,8: layer 2
    k_agg<<<AGG_BLOCKS, 256>>>(h1);
    k_gemm<<<GEMM_BLOCKS, 256, SM_TOTAL>>>(mp, h1, whi + 2 * 128 * 256, wlo + 2 * 128 * 256, bl[2], h0);
    // 9: final (+ deg zero for next call)
    k_final<<<AGG_BLOCKS, 256>>>(h0, Wf, bf, out);
}

// round 11
// speedup vs baseline: 1.6537x; 1.1100x over previous
#include <cuda_runtime.h>
#include <cuda_bf16.h>
#include <cstdint>

#define N_NODES 50000
#define N_EDGES 800000
#define F 128
#define NBLK_SCAN 196        // ceil(50000/256)

// ---------------- scratch (static device memory) -----------------------------
__device__ float g_h[2][(size_t)N_NODES * F];           // fp32 hidden (ping-pong)
__device__ float g_mean[(size_t)N_NODES * F];           // fp32 mean
__device__ __nv_bfloat16 g_whi[3 * 128 * 256];          // combined [Wl|Wr] hi
__device__ __nv_bfloat16 g_wlo[3 * 128 * 256];          // combined [Wl|Wr] lo
__device__ int g_deg[N_NODES];                          // zero-init; re-zeroed by k_final
__device__ int g_off[N_NODES];
__device__ int g_cursor[N_NODES];
__device__ int g_srcs[N_EDGES];
__device__ int g_blockagg[NBLK_SCAN];
__device__ int g_blockpref[NBLK_SCAN];
__device__ int g_aggdone;
__device__ int g_prefflag;

// ---------------- helpers ------------------------------------------------------
__device__ __forceinline__ unsigned smem_u32(const void* p) {
    unsigned a;
    asm("{ .reg .u64 t; cvta.to.shared.u64 t, %1; cvt.u32.u64 %0, t; }" : "=r"(a) : "l"(p));
    return a;
}
__device__ __forceinline__ void ldsm_x4(unsigned* r, unsigned addr) {
    asm volatile("ldmatrix.sync.aligned.m8n8.x4.shared.b16 {%0,%1,%2,%3}, [%4];"
                 : "=r"(r[0]), "=r"(r[1]), "=r"(r[2]), "=r"(r[3]) : "r"(addr));
}
__device__ __forceinline__ void mma16816(float* c, const unsigned* a, const unsigned* b) {
    asm volatile(
        "mma.sync.aligned.m16n8k16.row.col.f32.bf16.bf16.f32 "
        "{%0,%1,%2,%3}, {%4,%5,%6,%7}, {%8,%9}, {%0,%1,%2,%3};"
        : "+f"(c[0]), "+f"(c[1]), "+f"(c[2]), "+f"(c[3])
        : "r"(a[0]), "r"(a[1]), "r"(a[2]), "r"(a[3]), "r"(b[0]), "r"(b[1]));
}
// split two fp32 into (hi bf16x2 word, lo bf16x2 word); low half = first value
__device__ __forceinline__ void split2(float f0, float f1, unsigned& hw, unsigned& lw) {
    __nv_bfloat162 hb = __floats2bfloat162_rn(f0, f1);
    hw = *(unsigned*)&hb;
    float r0 = f0 - __uint_as_float(hw << 16);
    float r1 = f1 - __uint_as_float(hw & 0xFFFF0000u);
    __nv_bfloat162 lb = __floats2bfloat162_rn(r0, r1);
    lw = *(unsigned*)&lb;
}

// ---------------- launch 0: prep (pack W + hist + flag reset) --------------------
__global__ void k_prep(const int* __restrict__ edge,
                       const float* Wl0, const float* Wr0,
                       const float* Wl1, const float* Wr1,
                       const float* Wl2, const float* Wr2) {
    int gid = blockIdx.x * blockDim.x + threadIdx.x;
    if (gid == 0) { g_aggdone = 0; g_prefflag = 0; }
    if (gid < N_EDGES / 4) {
        uint4 d = *(const uint4*)(edge + N_EDGES + gid * 4);
        if (d.x < N_NODES) atomicAdd(&g_deg[d.x], 1);
        if (d.y < N_NODES) atomicAdd(&g_deg[d.y], 1);
        if (d.z < N_NODES) atomicAdd(&g_deg[d.z], 1);
        if (d.w < N_NODES) atomicAdd(&g_deg[d.w], 1);
    }
    if (gid < 3 * 128 * 256) {
        int L = gid / (128 * 256);
        int r = gid % (128 * 256);
        int n = r / 256;
        int k = r % 256;
        const float* Wl = (L == 0) ? Wl0 : (L == 1) ? Wl1 : Wl2;
        const float* Wr = (L == 0) ? Wr0 : (L == 1) ? Wr1 : Wr2;
        float v = (k < 128) ? Wl[n * 128 + k] : Wr[n * 128 + (k - 128)];
        __nv_bfloat16 h = __float2bfloat16(v);
        float r2 = v - __bfloat162float(h);
        g_whi[gid] = h;
        g_wlo[gid] = __float2bfloat16(r2);
    }
}

// ---------------- launch 1: single-kernel exclusive scan of deg -----------------
__global__ void __launch_bounds__(256, 8) k_scan() {
    __shared__ int s[256];
    __shared__ int ag[256];
    __shared__ int is_last;
    int b = blockIdx.x, t = threadIdx.x;
    int i = b * 256 + t;
    int v = (i < N_NODES) ? g_deg[i] : 0;
    s[t] = v;
    __syncthreads();
    for (int o = 1; o < 256; o <<= 1) {
        int x = (t >= o) ? s[t - o] : 0;
        __syncthreads();
        s[t] += x;
        __syncthreads();
    }
    if (t == 255) {
        g_blockagg[b] = s[255];
        __threadfence();
        is_last = (atomicAdd(&g_aggdone, 1) == NBLK_SCAN - 1);
    }
    __syncthreads();
    if (is_last) {
        int a = (t < NBLK_SCAN) ? ((volatile int*)g_blockagg)[t] : 0;
        ag[t] = a;
        __syncthreads();
        for (int o = 1; o < 256; o <<= 1) {
            int x = (t >= o) ? ag[t - o] : 0;
            __syncthreads();
            ag[t] += x;
            __syncthreads();
        }
        if (t < NBLK_SCAN) g_blockpref[t] = ag[t] - a;   // exclusive
        __threadfence();
        if (t == 0) atomicExch(&g_prefflag, 1);
    }
    if (t == 0) {
        while (((volatile int*)&g_prefflag)[0] == 0) { }
    }
    __syncthreads();
    int pref = ((volatile int*)g_blockpref)[b];
    if (i < N_NODES) {
        int off = pref + s[t] - v;
        g_off[i] = off;
        g_cursor[i] = off;
    }
}

// ---------------- launch 2: scatter ---------------------------------------------
__global__ void k_scatter(const int* __restrict__ edge) {
    int e4 = (blockIdx.x * blockDim.x + threadIdx.x) * 4;
    if (e4 + 3 < N_EDGES) {
        uint4 s = *(const uint4*)(edge + e4);
        uint4 d = *(const uint4*)(edge + N_EDGES + e4);
        if (d.x < N_NODES && s.x < N_NODES) g_srcs[atomicAdd(&g_cursor[d.x], 1)] = (int)s.x;
        if (d.y < N_NODES && s.y < N_NODES) g_srcs[atomicAdd(&g_cursor[d.y], 1)] = (int)s.y;
        if (d.z < N_NODES && s.z < N_NODES) g_srcs[atomicAdd(&g_cursor[d.z], 1)] = (int)s.z;
        if (d.w < N_NODES && s.w < N_NODES) g_srcs[atomicAdd(&g_cursor[d.w], 1)] = (int)s.w;
    } else {
        for (int e = e4; e < N_EDGES; e++) {
            unsigned src = (unsigned)edge[e];
            unsigned dst = (unsigned)edge[N_EDGES + e];
            if (dst < N_NODES && src < N_NODES)
                g_srcs[atomicAdd(&g_cursor[dst], 1)] = (int)src;
        }
    }
}

// ---------------- aggregation: one warp per node, fp32 gathers -------------------
__global__ void k_agg(const float* __restrict__ in) {
    int node = (blockIdx.x * blockDim.x + threadIdx.x) >> 5;
    if (node >= N_NODES) return;
    int lane = threadIdx.x & 31;
    int d = g_deg[node];
    int o = g_off[node];
    float a0 = 0.f, a1 = 0.f, a2 = 0.f, a3 = 0.f;
    for (int e = 0; e < d; e++) {
        int s = g_srcs[o + e];
        float4 v = ((const float4*)(in + (size_t)s * F))[lane];
        a0 += v.x; a1 += v.y; a2 += v.z; a3 += v.w;
    }
    float inv = (d > 0) ? 1.0f / (float)d : 0.0f;
    ((float4*)(g_mean + (size_t)node * F))[lane] =
        make_float4(a0 * inv, a1 * inv, a2 * inv, a3 * inv);
}

// ---------------- HMMA GEMM: fp32 A, split on the fly ----------------------------
#define SM_BIAS 0
#define SM_AHI  512
#define SM_ALO  (SM_AHI + 16384)
#define SM_WHI  (SM_ALO + 16384)
#define SM_WLO  (SM_WHI + 16384)
#define SM_TOTAL (SM_WLO + 16384)     // 66048 bytes

__device__ __forceinline__ unsigned swoff(int row, int k) {
    return (unsigned)(row * 128 + ((((k >> 3) ^ row) & 7) << 4) + (k & 7) * 2);
}

__global__ void __launch_bounds__(256, 1) k_gemm(
    const float* __restrict__ Am,
    const float* __restrict__ Ah,
    const __nv_bfloat16* __restrict__ Whi,
    const __nv_bfloat16* __restrict__ Wlo,
    const float* __restrict__ bl,
    float* __restrict__ outh)
{
    extern __shared__ __align__(16) char smem[];
    unsigned sb = smem_u32(smem);
    int tid = threadIdx.x;
    int wid = tid >> 5;
    int lane = tid & 31;
    int wm = wid & 1;
    int wn = wid >> 1;
    int m0 = blockIdx.x * 128;

    if (tid < 128) *(float*)(smem + SM_BIAS + tid * 4) = bl[tid];

    float acc[4][4][4];
#pragma unroll
    for (int a = 0; a < 4; a++)
#pragma unroll
        for (int b = 0; b < 4; b++)
#pragma unroll
            for (int c = 0; c < 4; c++) acc[a][b][c] = 0.f;

    for (int chunk = 0; chunk < 4; chunk++) {
        const float* ap = (chunk < 2) ? Am : Ah;
        int kcA = (chunk & 1) * 64;
        int kcW = chunk * 64;
        __syncthreads();
        // A chunk: 128 rows x 64 fp32 -> split into hi/lo bf16 planes
        for (int i = tid; i < 2048; i += 256) {
            int row = i >> 4;
            int k4 = (i & 15) * 4;
            float4 v = make_float4(0.f, 0.f, 0.f, 0.f);
            if (m0 + row < N_NODES)
                v = *(const float4*)(ap + (size_t)(m0 + row) * F + kcA + k4);
            uint2 h, l;
            split2(v.x, v.y, h.x, l.x);
            split2(v.z, v.w, h.y, l.y);
            unsigned off = swoff(row, k4);
            *(uint2*)(smem + SM_AHI + off) = h;
            *(uint2*)(smem + SM_ALO + off) = l;
        }
        for (int i = tid; i < 1024; i += 256) {
            int n = i >> 3;
            int k8 = (i & 7) * 8;
            unsigned off = swoff(n, k8);
            *(uint4*)(smem + SM_WHI + off) = *(const uint4*)(Whi + n * 256 + kcW + k8);
            *(uint4*)(smem + SM_WLO + off) = *(const uint4*)(Wlo + n * 256 + kcW + k8);
        }
        __syncthreads();

#pragma unroll
        for (int ks = 0; ks < 4; ks++) {
            int kl = ks * 16;
            unsigned ahi[16], alo[16];
            int mrl = ((lane >> 3) & 1) * 8 + (lane & 7);
            int kkA = kl + (lane >> 4) * 8;
#pragma unroll
            for (int mf = 0; mf < 4; mf++) {
                int mrow = wm * 64 + mf * 16 + mrl;
                unsigned offA = (unsigned)(mrow * 128 + ((((kkA >> 3) ^ mrow) & 7) << 4));
                ldsm_x4(&ahi[mf * 4], sb + SM_AHI + offA);
                ldsm_x4(&alo[mf * 4], sb + SM_ALO + offA);
            }
            unsigned bhi[8], blo[8];
            int nrl = (lane >> 4) * 8 + (lane & 7);
            int kkB = kl + ((lane >> 3) & 1) * 8;
#pragma unroll
            for (int nf2 = 0; nf2 < 2; nf2++) {
                int nrow = wn * 32 + nf2 * 16 + nrl;
                unsigned offB = (unsigned)(nrow * 128 + ((((kkB >> 3) ^ nrow) & 7) << 4));
                ldsm_x4(&bhi[nf2 * 4], sb + SM_WHI + offB);
                ldsm_x4(&blo[nf2 * 4], sb + SM_WLO + offB);
            }
#pragma unroll
            for (int mf = 0; mf < 4; mf++)
#pragma unroll
                for (int nf = 0; nf < 4; nf++) {
                    const unsigned* bh = &bhi[(nf >> 1) * 4 + (nf & 1) * 2];
                    const unsigned* blp = &blo[(nf >> 1) * 4 + (nf & 1) * 2];
                    mma16816(acc[mf][nf], &ahi[mf * 4], bh);
                    mma16816(acc[mf][nf], &ahi[mf * 4], blp);
                    mma16816(acc[mf][nf], &alo[mf * 4], bh);
                }
        }
    }

    // epilogue: bias + relu, plain fp32 stores
    const float* bias = (const float*)(smem + SM_BIAS);
#pragma unroll
    for (int mf = 0; mf < 4; mf++) {
        int ra = m0 + wm * 64 + mf * 16 + (lane >> 2);
        int rb = ra + 8;
#pragma unroll
        for (int nf = 0; nf < 4; nf++) {
            int col = wn * 32 + nf * 8 + (lane & 3) * 2;
            float b0 = bias[col], b1 = bias[col + 1];
            if (ra < N_NODES) {
                float v0 = fmaxf(acc[mf][nf][0] + b0, 0.f);
                float v1 = fmaxf(acc[mf][nf][1] + b1, 0.f);
                *(float2*)(outh + (size_t)ra * F + col) = make_float2(v0, v1);
            }
            if (rb < N_NODES) {
                float v2 = fmaxf(acc[mf][nf][2] + b0, 0.f);
                float v3 = fmaxf(acc[mf][nf][3] + b1, 0.f);
                *(float2*)(outh + (size_t)rb * F + col) = make_float2(v2, v3);
            }
        }
    }
}

// ---------------- final linear + deg re-zero for next call ----------------------
__global__ void k_final(const float* __restrict__ h,
                        const float* __restrict__ Wf,
                        const float* __restrict__ bf,
                        float* __restrict__ out)
{
    int gid = blockIdx.x * blockDim.x + threadIdx.x;
    if (gid < N_NODES) g_deg[gid] = 0;        // prep for next call's histogram
    int node = gid >> 5;
    if (node >= N_NODES) return;
    int lane = gid & 31;
    float4 hv = ((const float4*)(h + (size_t)node * F))[lane];
    float4 wv = ((const float4*)Wf)[lane];
    float s = hv.x * wv.x + hv.y * wv.y + hv.z * wv.z + hv.w * wv.w;
#pragma unroll
    for (int o = 16; o > 0; o >>= 1) s += __shfl_down_sync(0xFFFFFFFFu, s, o);
    if (lane == 0) out[node] = s + bf[0];
}

// ---------------- launch ------------------------------------------------------------
extern "C" void kernel_launch(void* const* d_in, const int* in_sizes, int n_in,
                              void* d_out, int out_size)
{
    const float* x    = (const float*)d_in[0];
    const int*   edge = (const int*)d_in[1];   // int32 (JAX x64 disabled)
    const float* Wl[3] = {(const float*)d_in[2], (const float*)d_in[5], (const float*)d_in[8]};
    const float* bl[3] = {(const float*)d_in[3], (const float*)d_in[6], (const float*)d_in[9]};
    const float* Wr[3] = {(const float*)d_in[4], (const float*)d_in[7], (const float*)d_in[10]};
    const float* Wf = (const float*)d_in[11];
    const float* bf = (const float*)d_in[12];
    float* out = (float*)d_out;

    cudaFuncSetAttribute(k_gemm, cudaFuncAttributeMaxDynamicSharedMemorySize, SM_TOTAL);

    void* p = nullptr;
    cudaGetSymbolAddress(&p, g_h);
    float* h0 = (float*)p;
    float* h1 = h0 + (size_t)N_NODES * F;
    cudaGetSymbolAddress(&p, g_mean);
    float* mp = (float*)p;
    cudaGetSymbolAddress(&p, g_whi);
    __nv_bfloat16* whi = (__nv_bfloat16*)p;
    cudaGetSymbolAddress(&p, g_wlo);
    __nv_bfloat16* wlo = (__nv_bfloat16*)p;

    const int AGG_BLOCKS = (N_NODES * 32 + 255) / 256;
    const int GEMM_BLOCKS = (N_NODES + 127) / 128;   // 391

    // 0: prep (pack W + histogram + flag reset)
    k_prep<<<(N_EDGES / 4 + 255) / 256, 256>>>(edge, Wl[0], Wr[0], Wl[1], Wr[1], Wl[2], Wr[2]);
    // 1: scan  2: scatter
    k_scan<<<NBLK_SCAN, 256>>>();
    k_scatter<<<(N_EDGES / 4 + 255) / 256, 256>>>(edge);

    // 3: agg0 (ncu capture slot)  4: gemm0
    k_agg<<<AGG_BLOCKS, 256>>>(x);
    k_gemm<<<GEMM_BLOCKS, 256, SM_TOTAL>>>(mp, x, whi, wlo, bl[0], h0);
    // 5,6: layer 1
    k_agg<<<AGG_BLOCKS, 256>>>(h0);
    k_gemm<<<GEMM_BLOCKS, 256, SM_TOTAL>>>(mp, h0, whi + 128 * 256, wlo + 128 * 256, bl[1], h1);
    // 7,8: layer 2
    k_agg<<<AGG_BLOCKS, 256>>>(h1);
    k_gemm<<<GEMM_BLOCKS, 256, SM_TOTAL>>>(mp, h1, whi + 2 * 128 * 256, wlo + 2 * 128 * 256, bl[2], h0);
    // 9: final (+ deg zero for next call)
    k_final<<<AGG_BLOCKS, 256>>>(h0, Wf, bf, out);
}

// round 12
// speedup vs baseline: 1.9395x; 1.1728x over previous
#include <cuda_runtime.h>
#include <cuda_bf16.h>
#include <cstdint>

#define N_NODES 50000
#define N_EDGES 800000
#define F 128
#define NBLK_SCAN 196        // ceil(50000/256)

// ---------------- scratch (static device memory) -----------------------------
__device__ float g_h[2][(size_t)N_NODES * F];           // fp32 hidden (ping-pong)
__device__ float g_mean[(size_t)N_NODES * F];           // fp32 mean
__device__ __nv_bfloat16 g_whi[3 * 128 * 256];          // combined [Wl|Wr] hi
__device__ __nv_bfloat16 g_wlo[3 * 128 * 256];          // combined [Wl|Wr] lo
__device__ int g_deg[N_NODES];                          // zero-init; re-zeroed by k_final
__device__ int g_off[N_NODES];
__device__ int g_cursor[N_NODES];
__device__ int g_srcs[N_EDGES];
__device__ int g_blockagg[NBLK_SCAN];
__device__ int g_blockpref[NBLK_SCAN];
__device__ int g_aggdone;
__device__ int g_prefflag;

// ---------------- helpers ------------------------------------------------------
__device__ __forceinline__ unsigned smem_u32(const void* p) {
    unsigned a;
    asm("{ .reg .u64 t; cvta.to.shared.u64 t, %1; cvt.u32.u64 %0, t; }" : "=r"(a) : "l"(p));
    return a;
}
__device__ __forceinline__ void ldsm_x4(unsigned* r, unsigned addr) {
    asm volatile("ldmatrix.sync.aligned.m8n8.x4.shared.b16 {%0,%1,%2,%3}, [%4];"
                 : "=r"(r[0]), "=r"(r[1]), "=r"(r[2]), "=r"(r[3]) : "r"(addr));
}
__device__ __forceinline__ void mma16816(float* c, const unsigned* a, const unsigned* b) {
    asm volatile(
        "mma.sync.aligned.m16n8k16.row.col.f32.bf16.bf16.f32 "
        "{%0,%1,%2,%3}, {%4,%5,%6,%7}, {%8,%9}, {%0,%1,%2,%3};"
        : "+f"(c[0]), "+f"(c[1]), "+f"(c[2]), "+f"(c[3])
        : "r"(a[0]), "r"(a[1]), "r"(a[2]), "r"(a[3]), "r"(b[0]), "r"(b[1]));
}
__device__ __forceinline__ void split2(float f0, float f1, unsigned& hw, unsigned& lw) {
    __nv_bfloat162 hb = __floats2bfloat162_rn(f0, f1);
    hw = *(unsigned*)&hb;
    float r0 = f0 - __uint_as_float(hw << 16);
    float r1 = f1 - __uint_as_float(hw & 0xFFFF0000u);
    __nv_bfloat162 lb = __floats2bfloat162_rn(r0, r1);
    lw = *(unsigned*)&lb;
}
__device__ __forceinline__ void cp16(unsigned dst, const void* src) {
    asm volatile("cp.async.cg.shared.global [%0], [%1], 16;" :: "r"(dst), "l"(src));
}
#define CP_COMMIT() asm volatile("cp.async.commit_group;" ::: "memory")
#define CP_WAIT0()  asm volatile("cp.async.wait_group 0;" ::: "memory")

// ---------------- launch 0: prep (pack W + hist + flag reset) --------------------
__global__ void k_prep(const int* __restrict__ edge,
                       const float* Wl0, const float* Wr0,
                       const float* Wl1, const float* Wr1,
                       const float* Wl2, const float* Wr2) {
    int gid = blockIdx.x * blockDim.x + threadIdx.x;
    if (gid == 0) { g_aggdone = 0; g_prefflag = 0; }
    if (gid < N_EDGES / 4) {
        uint4 d = *(const uint4*)(edge + N_EDGES + gid * 4);
        if (d.x < N_NODES) atomicAdd(&g_deg[d.x], 1);
        if (d.y < N_NODES) atomicAdd(&g_deg[d.y], 1);
        if (d.z < N_NODES) atomicAdd(&g_deg[d.z], 1);
        if (d.w < N_NODES) atomicAdd(&g_deg[d.w], 1);
    }
    if (gid < 3 * 128 * 256) {
        int L = gid / (128 * 256);
        int r = gid % (128 * 256);
        int n = r / 256;
        int k = r % 256;
        const float* Wl = (L == 0) ? Wl0 : (L == 1) ? Wl1 : Wl2;
        const float* Wr = (L == 0) ? Wr0 : (L == 1) ? Wr1 : Wr2;
        float v = (k < 128) ? Wl[n * 128 + k] : Wr[n * 128 + (k - 128)];
        __nv_bfloat16 h = __float2bfloat16(v);
        float r2 = v - __bfloat162float(h);
        g_whi[gid] = h;
        g_wlo[gid] = __float2bfloat16(r2);
    }
}

// ---------------- launch 1: fused scan + scatter (grid-resident) ----------------
#define EDGES_PER_BLK 1021    // 196*1021*4 >= 800000 (in units of 4 edges)
__global__ void __launch_bounds__(256, 8) k_scan_scatter(const int* __restrict__ edge) {
    __shared__ int s[256];
    __shared__ int ag[256];
    __shared__ int is_last;
    int b = blockIdx.x, t = threadIdx.x;
    int i = b * 256 + t;
    int v = (i < N_NODES) ? g_deg[i] : 0;
    s[t] = v;
    __syncthreads();
    for (int o = 1; o < 256; o <<= 1) {
        int x = (t >= o) ? s[t - o] : 0;
        __syncthreads();
        s[t] += x;
        __syncthreads();
    }
    if (t == 255) {
        g_blockagg[b] = s[255];
        __threadfence();
        is_last = (atomicAdd(&g_aggdone, 1) == NBLK_SCAN - 1);
    }
    __syncthreads();
    if (is_last) {
        int a = (t < NBLK_SCAN) ? ((volatile int*)g_blockagg)[t] : 0;
        ag[t] = a;
        __syncthreads();
        for (int o = 1; o < 256; o <<= 1) {
            int x = (t >= o) ? ag[t - o] : 0;
            __syncthreads();
            ag[t] += x;
            __syncthreads();
        }
        if (t < NBLK_SCAN) g_blockpref[t] = ag[t] - a;   // exclusive
        __threadfence();
        if (t == 0) atomicExch(&g_prefflag, 1);
    }
    if (t == 0) {
        while (((volatile int*)&g_prefflag)[0] == 0) { }
    }
    __syncthreads();
    int pref = ((volatile int*)g_blockpref)[b];
    if (i < N_NODES) {
        int off = pref + s[t] - v;
        g_off[i] = off;
        g_cursor[i] = off;
    }
    // cursors for this block's nodes are set, but scatter hits arbitrary dst:
    // need ALL cursors ready -> grid-wide: second flag round not needed because
    // every block spins on g_prefflag THEN writes its own cursors; we must wait
    // until all blocks wrote cursors. Use a second arrival counter.
    __threadfence();
    __shared__ int all_done;
    if (t == 0) {
        int n = atomicAdd(&g_aggdone, 1);          // counts 196..391
        all_done = n;
        while (((volatile int*)&g_aggdone)[0] < 2 * NBLK_SCAN) { }
    }
    __syncthreads();
    // scatter: each block owns EDGES_PER_BLK groups of 4 edges
    int base4 = b * EDGES_PER_BLK;
    for (int j = t; j < EDGES_PER_BLK; j += 256) {
        int e4 = (base4 + j) * 4;
        if (e4 + 3 < N_EDGES) {
            uint4 sv = *(const uint4*)(edge + e4);
            uint4 dv = *(const uint4*)(edge + N_EDGES + e4);
            if (dv.x < N_NODES && sv.x < N_NODES) g_srcs[atomicAdd(&g_cursor[dv.x], 1)] = (int)sv.x;
            if (dv.y < N_NODES && sv.y < N_NODES) g_srcs[atomicAdd(&g_cursor[dv.y], 1)] = (int)sv.y;
            if (dv.z < N_NODES && sv.z < N_NODES) g_srcs[atomicAdd(&g_cursor[dv.z], 1)] = (int)sv.z;
            if (dv.w < N_NODES && sv.w < N_NODES) g_srcs[atomicAdd(&g_cursor[dv.w], 1)] = (int)sv.w;
        } else if (e4 < N_EDGES) {
            for (int e = e4; e < N_EDGES; e++) {
                unsigned src = (unsigned)edge[e];
                unsigned dst = (unsigned)edge[N_EDGES + e];
                if (dst < N_NODES && src < N_NODES)
                    g_srcs[atomicAdd(&g_cursor[dst], 1)] = (int)src;
            }
        }
    }
}

// ---------------- aggregation: one warp per node (R11 exact) --------------------
__global__ void k_agg(const float* __restrict__ in) {
    int node = (blockIdx.x * blockDim.x + threadIdx.x) >> 5;
    if (node >= N_NODES) return;
    int lane = threadIdx.x & 31;
    int d = g_deg[node];
    int o = g_off[node];
    float a0 = 0.f, a1 = 0.f, a2 = 0.f, a3 = 0.f;
    for (int e = 0; e < d; e++) {
        int s = g_srcs[o + e];
        float4 v = ((const float4*)(in + (size_t)s * F))[lane];
        a0 += v.x; a1 += v.y; a2 += v.z; a3 += v.w;
    }
    float inv = (d > 0) ? 1.0f / (float)d : 0.0f;
    ((float4*)(g_mean + (size_t)node * F))[lane] =
        make_float4(a0 * inv, a1 * inv, a2 * inv, a3 * inv);
}

// ---------------- HMMA GEMM: cp.async double-buffered pipeline ------------------
#define SM_BIAS  0
#define SM_ARAW0 1024
#define SM_ARAW1 (SM_ARAW0 + 32768)
#define SM_AHI   (SM_ARAW1 + 32768)
#define SM_ALO   (SM_AHI + 16384)
#define SM_WHI0  (SM_ALO + 16384)
#define SM_WLO0  (SM_WHI0 + 16384)
#define SM_WHI1  (SM_WLO0 + 16384)
#define SM_WLO1  (SM_WHI1 + 16384)
#define SM_TOTAL (SM_WLO1 + 16384)   // 164864 bytes

__device__ __forceinline__ unsigned swoff(int row, int k) {
    return (unsigned)(row * 128 + ((((k >> 3) ^ row) & 7) << 4) + (k & 7) * 2);
}

__device__ __forceinline__ void issue_chunk(
    int chunk, unsigned sb, int tid, int m0,
    const float* Am, const float* Ah,
    const __nv_bfloat16* Whi, const __nv_bfloat16* Wlo)
{
    const float* ap = (chunk < 2) ? Am : Ah;
    int kcA = (chunk & 1) * 64;
    int kcW = chunk * 64;
    int buf = chunk & 1;
    unsigned araw = sb + (buf ? SM_ARAW1 : SM_ARAW0);
    unsigned whb = sb + (buf ? SM_WHI1 : SM_WHI0);
    unsigned wlb = sb + (buf ? SM_WLO1 : SM_WLO0);
#pragma unroll
    for (int q = 0; q < 8; q++) {
        int i = tid + q * 256;             // 0..2047
        int row = i >> 4;
        int k4 = (i & 15) * 4;
        int gr = m0 + row;
        if (gr >= N_NODES) gr = N_NODES - 1;   // clamp; OOB rows' outputs discarded
        cp16(araw + row * 256 + k4 * 4, ap + (size_t)gr * F + kcA + k4);
    }
#pragma unroll
    for (int q = 0; q < 4; q++) {
        int i = tid + q * 256;             // 0..1023
        int n = i >> 3;
        int k8 = (i & 7) * 8;
        unsigned off = swoff(n, k8);
        cp16(whb + off, Whi + n * 256 + kcW + k8);
        cp16(wlb + off, Wlo + n * 256 + kcW + k8);
    }
}

__global__ void __launch_bounds__(256, 1) k_gemm(
    const float* __restrict__ Am,
    const float* __restrict__ Ah,
    const __nv_bfloat16* __restrict__ Whi,
    const __nv_bfloat16* __restrict__ Wlo,
    const float* __restrict__ bl,
    float* __restrict__ outh)
{
    extern __shared__ __align__(16) char smem[];
    unsigned sb = smem_u32(smem);
    int tid = threadIdx.x;
    int wid = tid >> 5;
    int lane = tid & 31;
    int wm = wid & 1;
    int wn = wid >> 1;
    int m0 = blockIdx.x * 128;

    if (tid < 128) *(float*)(smem + SM_BIAS + tid * 4) = bl[tid];

    float acc[4][4][4];
#pragma unroll
    for (int a = 0; a < 4; a++)
#pragma unroll
        for (int b = 0; b < 4; b++)
#pragma unroll
            for (int c = 0; c < 4; c++) acc[a][b][c] = 0.f;

    // prologue: prefetch chunk 0
    issue_chunk(0, sb, tid, m0, Am, Ah, Whi, Wlo);
    CP_COMMIT();

    for (int chunk = 0; chunk < 4; chunk++) {
        int buf = chunk & 1;
        CP_WAIT0();             // chunk's data landed
        __syncthreads();        // all threads done with prev MMA + data visible
        if (chunk < 3) {        // prefetch next into other buffers
            issue_chunk(chunk + 1, sb, tid, m0, Am, Ah, Whi, Wlo);
            CP_COMMIT();
        }
        // split raw fp32 A (smem) -> hi/lo bf16 planes
        {
            unsigned araw = (buf ? SM_ARAW1 : SM_ARAW0);
#pragma unroll
            for (int q = 0; q < 8; q++) {
                int i = tid + q * 256;
                int row = i >> 4;
                int k4 = (i & 15) * 4;
                float4 v = *(const float4*)(smem + araw + row * 256 + k4 * 4);
                uint2 h, l;
                split2(v.x, v.y, h.x, l.x);
                split2(v.z, v.w, h.y, l.y);
                unsigned off = swoff(row, k4);
                *(uint2*)(smem + SM_AHI + off) = h;
                *(uint2*)(smem + SM_ALO + off) = l;
            }
        }
        __syncthreads();

        unsigned whb = sb + (buf ? SM_WHI1 : SM_WHI0);
        unsigned wlb = sb + (buf ? SM_WLO1 : SM_WLO0);
#pragma unroll
        for (int ks = 0; ks < 4; ks++) {
            int kl = ks * 16;
            unsigned ahi[16], alo[16];
            int mrl = ((lane >> 3) & 1) * 8 + (lane & 7);
            int kkA = kl + (lane >> 4) * 8;
#pragma unroll
            for (int mf = 0; mf < 4; mf++) {
                int mrow = wm * 64 + mf * 16 + mrl;
                unsigned offA = (unsigned)(mrow * 128 + ((((kkA >> 3) ^ mrow) & 7) << 4));
                ldsm_x4(&ahi[mf * 4], sb + SM_AHI + offA);
                ldsm_x4(&alo[mf * 4], sb + SM_ALO + offA);
            }
            unsigned bhi[8], blo[8];
            int nrl = (lane >> 4) * 8 + (lane & 7);
            int kkB = kl + ((lane >> 3) & 1) * 8;
#pragma unroll
            for (int nf2 = 0; nf2 < 2; nf2++) {
                int nrow = wn * 32 + nf2 * 16 + nrl;
                unsigned offB = (unsigned)(nrow * 128 + ((((kkB >> 3) ^ nrow) & 7) << 4));
                ldsm_x4(&bhi[nf2 * 4], whb + offB);
                ldsm_x4(&blo[nf2 * 4], wlb + offB);
            }
#pragma unroll
            for (int mf = 0; mf < 4; mf++)
#pragma unroll
                for (int nf = 0; nf < 4; nf++) {
                    const unsigned* bh = &bhi[(nf >> 1) * 4 + (nf & 1) * 2];
                    const unsigned* blp = &blo[(nf >> 1) * 4 + (nf & 1) * 2];
                    mma16816(acc[mf][nf], &ahi[mf * 4], bh);
                    mma16816(acc[mf][nf], &ahi[mf * 4], blp);
                    mma16816(acc[mf][nf], &alo[mf * 4], bh);
                }
        }
    }

    // epilogue: bias + relu, fp32 stores
    const float* bias = (const float*)(smem + SM_BIAS);
#pragma unroll
    for (int mf = 0; mf < 4; mf++) {
        int ra = m0 + wm * 64 + mf * 16 + (lane >> 2);
        int rb = ra + 8;
#pragma unroll
        for (int nf = 0; nf < 4; nf++) {
            int col = wn * 32 + nf * 8 + (lane & 3) * 2;
            float b0 = bias[col], b1 = bias[col + 1];
            if (ra < N_NODES) {
                float v0 = fmaxf(acc[mf][nf][0] + b0, 0.f);
                float v1 = fmaxf(acc[mf][nf][1] + b1, 0.f);
                *(float2*)(outh + (size_t)ra * F + col) = make_float2(v0, v1);
            }
            if (rb < N_NODES) {
                float v2 = fmaxf(acc[mf][nf][2] + b0, 0.f);
                float v3 = fmaxf(acc[mf][nf][3] + b1, 0.f);
                *(float2*)(outh + (size_t)rb * F + col) = make_float2(v2, v3);
            }
        }
    }
}

// ---------------- final linear + deg re-zero for next call ----------------------
__global__ void k_final(const float* __restrict__ h,
                        const float* __restrict__ Wf,
                        const float* __restrict__ bf,
                        float* __restrict__ out)
{
    int gid = blockIdx.x * blockDim.x + threadIdx.x;
    if (gid < N_NODES) g_deg[gid] = 0;        // prep for next call's histogram
    int node = gid >> 5;
    if (node >= N_NODES) return;
    int lane = gid & 31;
    float4 hv = ((const float4*)(h + (size_t)node * F))[lane];
    float4 wv = ((const float4*)Wf)[lane];
    float s = hv.x * wv.x + hv.y * wv.y + hv.z * wv.z + hv.w * wv.w;
#pragma unroll
    for (int o = 16; o > 0; o >>= 1) s += __shfl_down_sync(0xFFFFFFFFu, s, o);
    if (lane == 0) out[node] = s + bf[0];
}

// ---------------- launch ------------------------------------------------------------
extern "C" void kernel_launch(void* const* d_in, const int* in_sizes, int n_in,
                              void* d_out, int out_size)
{
    const float* x    = (const float*)d_in[0];
    const int*   edge = (const int*)d_in[1];   // int32 (JAX x64 disabled)
    const float* Wl[3] = {(const float*)d_in[2], (const float*)d_in[5], (const float*)d_in[8]};
    const float* bl[3] = {(const float*)d_in[3], (const float*)d_in[6], (const float*)d_in[9]};
    const float* Wr[3] = {(const float*)d_in[4], (const float*)d_in[7], (const float*)d_in[10]};
    const float* Wf = (const float*)d_in[11];
    const float* bf = (const float*)d_in[12];
    float* out = (float*)d_out;

    cudaFuncSetAttribute(k_gemm, cudaFuncAttributeMaxDynamicSharedMemorySize, SM_TOTAL);

    void* p = nullptr;
    cudaGetSymbolAddress(&p, g_h);
    float* h0 = (float*)p;
    float* h1 = h0 + (size_t)N_NODES * F;
    cudaGetSymbolAddress(&p, g_mean);
    float* mp = (float*)p;
    cudaGetSymbolAddress(&p, g_whi);
    __nv_bfloat16* whi = (__nv_bfloat16*)p;
    cudaGetSymbolAddress(&p, g_wlo);
    __nv_bfloat16* wlo = (__nv_bfloat16*)p;

    const int AGG_BLOCKS = (N_NODES * 32 + 255) / 256;
    const int GEMM_BLOCKS = (N_NODES + 127) / 128;   // 391

    // 0: prep (pack W + histogram + flag reset)
    k_prep<<<(N_EDGES / 4 + 255) / 256, 256>>>(edge, Wl[0], Wr[0], Wl[1], Wr[1], Wl[2], Wr[2]);
    // 1: fused scan + scatter
    k_scan_scatter<<<NBLK_SCAN, 256>>>(edge);

    // 2: agg0   3: gemm0 (ncu capture slot)
    k_agg<<<AGG_BLOCKS, 256>>>(x);
    k_gemm<<<GEMM_BLOCKS, 256, SM_TOTAL>>>(mp, x, whi, wlo, bl[0], h0);
    // 4,5: layer 1
    k_agg<<<AGG_BLOCKS, 256>>>(h0);
    k_gemm<<<GEMM_BLOCKS, 256, SM_TOTAL>>>(mp, h0, whi + 128 * 256, wlo + 128 * 256, bl[1], h1);
    // 6,7: layer 2
    k_agg<<<AGG_BLOCKS, 256>>>(h1);
    k_gemm<<<GEMM_BLOCKS, 256, SM_TOTAL>>>(mp, h1, whi + 2 * 128 * 256, wlo + 2 * 128 * 256, bl[2], h0);
    // 8: final (+ deg zero for next call)
    k_final<<<AGG_BLOCKS, 256>>>(h0, Wf, bf, out);
}

// round 13
// speedup vs baseline: 1.9700x; 1.0157x over previous
#include <cuda_runtime.h>
#include <cuda_bf16.h>
#include <cstdint>

#define N_NODES 50000
#define N_EDGES 800000
#define F 128
#define NBLK_SCAN 196        // ceil(50000/256)

// ---------------- scratch (static device memory) -----------------------------
__device__ float g_h[2][(size_t)N_NODES * F];           // fp32 hidden (ping-pong)
__device__ float g_mean[(size_t)N_NODES * F];           // fp32 mean
__device__ __nv_bfloat16 g_whi[3 * 128 * 256];          // combined [Wl|Wr] hi
__device__ __nv_bfloat16 g_wlo[3 * 128 * 256];          // combined [Wl|Wr] lo
__device__ int g_deg[N_NODES];                          // zero-init; re-zeroed by k_final
__device__ int g_off[N_NODES];
__device__ int g_cursor[N_NODES];
__device__ int g_srcs[N_EDGES];
__device__ int g_blockagg[NBLK_SCAN];
__device__ int g_blockpref[NBLK_SCAN];
__device__ int g_aggdone;
__device__ int g_prefflag;

// ---------------- helpers ------------------------------------------------------
__device__ __forceinline__ unsigned smem_u32(const void* p) {
    unsigned a;
    asm("{ .reg .u64 t; cvta.to.shared.u64 t, %1; cvt.u32.u64 %0, t; }" : "=r"(a) : "l"(p));
    return a;
}
__device__ __forceinline__ void ldsm_x4(unsigned* r, unsigned addr) {
    asm volatile("ldmatrix.sync.aligned.m8n8.x4.shared.b16 {%0,%1,%2,%3}, [%4];"
                 : "=r"(r[0]), "=r"(r[1]), "=r"(r[2]), "=r"(r[3]) : "r"(addr));
}
__device__ __forceinline__ void mma16816(float* c, const unsigned* a, const unsigned* b) {
    asm volatile(
        "mma.sync.aligned.m16n8k16.row.col.f32.bf16.bf16.f32 "
        "{%0,%1,%2,%3}, {%4,%5,%6,%7}, {%8,%9}, {%0,%1,%2,%3};"
        : "+f"(c[0]), "+f"(c[1]), "+f"(c[2]), "+f"(c[3])
        : "r"(a[0]), "r"(a[1]), "r"(a[2]), "r"(a[3]), "r"(b[0]), "r"(b[1]));
}
__device__ __forceinline__ void split2(float f0, float f1, unsigned& hw, unsigned& lw) {
    __nv_bfloat162 hb = __floats2bfloat162_rn(f0, f1);
    hw = *(unsigned*)&hb;
    float r0 = f0 - __uint_as_float(hw << 16);
    float r1 = f1 - __uint_as_float(hw & 0xFFFF0000u);
    __nv_bfloat162 lb = __floats2bfloat162_rn(r0, r1);
    lw = *(unsigned*)&lb;
}
__device__ __forceinline__ void cp16(unsigned dst, const void* src) {
    asm volatile("cp.async.cg.shared.global [%0], [%1], 16;" :: "r"(dst), "l"(src));
}
#define CP_COMMIT() asm volatile("cp.async.commit_group;" ::: "memory")
#define CP_WAIT0()  asm volatile("cp.async.wait_group 0;" ::: "memory")

// ---------------- launch 0: prep (pack W + hist + flag reset) --------------------
__global__ void k_prep(const int* __restrict__ edge,
                       const float* Wl0, const float* Wr0,
                       const float* Wl1, const float* Wr1,
                       const float* Wl2, const float* Wr2) {
    int gid = blockIdx.x * blockDim.x + threadIdx.x;
    if (gid == 0) { g_aggdone = 0; g_prefflag = 0; }
    if (gid < N_EDGES / 4) {
        uint4 d = *(const uint4*)(edge + N_EDGES + gid * 4);
        if (d.x < N_NODES) atomicAdd(&g_deg[d.x], 1);
        if (d.y < N_NODES) atomicAdd(&g_deg[d.y], 1);
        if (d.z < N_NODES) atomicAdd(&g_deg[d.z], 1);
        if (d.w < N_NODES) atomicAdd(&g_deg[d.w], 1);
    }
    if (gid < 3 * 128 * 256) {
        int L = gid / (128 * 256);
        int r = gid % (128 * 256);
        int n = r / 256;
        int k = r % 256;
        const float* Wl = (L == 0) ? Wl0 : (L == 1) ? Wl1 : Wl2;
        const float* Wr = (L == 0) ? Wr0 : (L == 1) ? Wr1 : Wr2;
        float v = (k < 128) ? Wl[n * 128 + k] : Wr[n * 128 + (k - 128)];
        __nv_bfloat16 h = __float2bfloat16(v);
        float r2 = v - __bfloat162float(h);
        g_whi[gid] = h;
        g_wlo[gid] = __float2bfloat16(r2);
    }
}

// ---------------- launch 1: fused scan + scatter (grid-resident) ----------------
#define EDGES_PER_BLK 1021    // 196*1021*4 >= 800000 (units of 4 edges)
__global__ void __launch_bounds__(256, 8) k_scan_scatter(const int* __restrict__ edge) {
    __shared__ int s[256];
    __shared__ int ag[256];
    __shared__ int is_last;
    int b = blockIdx.x, t = threadIdx.x;
    int i = b * 256 + t;
    int v = (i < N_NODES) ? g_deg[i] : 0;
    s[t] = v;
    __syncthreads();
    for (int o = 1; o < 256; o <<= 1) {
        int x = (t >= o) ? s[t - o] : 0;
        __syncthreads();
        s[t] += x;
        __syncthreads();
    }
    if (t == 255) {
        g_blockagg[b] = s[255];
        __threadfence();
        is_last = (atomicAdd(&g_aggdone, 1) == NBLK_SCAN - 1);
    }
    __syncthreads();
    if (is_last) {
        int a = (t < NBLK_SCAN) ? ((volatile int*)g_blockagg)[t] : 0;
        ag[t] = a;
        __syncthreads();
        for (int o = 1; o < 256; o <<= 1) {
            int x = (t >= o) ? ag[t - o] : 0;
            __syncthreads();
            ag[t] += x;
            __syncthreads();
        }
        if (t < NBLK_SCAN) g_blockpref[t] = ag[t] - a;   // exclusive
        __threadfence();
        if (t == 0) atomicExch(&g_prefflag, 1);
    }
    if (t == 0) {
        while (((volatile int*)&g_prefflag)[0] == 0) { }
    }
    __syncthreads();
    int pref = ((volatile int*)g_blockpref)[b];
    if (i < N_NODES) {
        int off = pref + s[t] - v;
        g_off[i] = off;
        g_cursor[i] = off;
    }
    __threadfence();
    if (t == 0) {
        atomicAdd(&g_aggdone, 1);                       // counts 196..392
        while (((volatile int*)&g_aggdone)[0] < 2 * NBLK_SCAN) { }
    }
    __syncthreads();
    // scatter: each block owns EDGES_PER_BLK groups of 4 edges
    int base4 = b * EDGES_PER_BLK;
    for (int j = t; j < EDGES_PER_BLK; j += 256) {
        int e4 = (base4 + j) * 4;
        if (e4 + 3 < N_EDGES) {
            uint4 sv = *(const uint4*)(edge + e4);
            uint4 dv = *(const uint4*)(edge + N_EDGES + e4);
            if (dv.x < N_NODES && sv.x < N_NODES) g_srcs[atomicAdd(&g_cursor[dv.x], 1)] = (int)sv.x;
            if (dv.y < N_NODES && sv.y < N_NODES) g_srcs[atomicAdd(&g_cursor[dv.y], 1)] = (int)sv.y;
            if (dv.z < N_NODES && sv.z < N_NODES) g_srcs[atomicAdd(&g_cursor[dv.z], 1)] = (int)sv.z;
            if (dv.w < N_NODES && sv.w < N_NODES) g_srcs[atomicAdd(&g_cursor[dv.w], 1)] = (int)sv.w;
        } else if (e4 < N_EDGES) {
            for (int e = e4; e < N_EDGES; e++) {
                unsigned src = (unsigned)edge[e];
                unsigned dst = (unsigned)edge[N_EDGES + e];
                if (dst < N_NODES && src < N_NODES)
                    g_srcs[atomicAdd(&g_cursor[dst], 1)] = (int)src;
            }
        }
    }
}

// ---------------- aggregation: one warp per node (R11 exact) --------------------
__global__ void k_agg(const float* __restrict__ in) {
    int node = (blockIdx.x * blockDim.x + threadIdx.x) >> 5;
    if (node >= N_NODES) return;
    int lane = threadIdx.x & 31;
    int d = g_deg[node];
    int o = g_off[node];
    float a0 = 0.f, a1 = 0.f, a2 = 0.f, a3 = 0.f;
    for (int e = 0; e < d; e++) {
        int s = g_srcs[o + e];
        float4 v = ((const float4*)(in + (size_t)s * F))[lane];
        a0 += v.x; a1 += v.y; a2 += v.z; a3 += v.w;
    }
    float inv = (d > 0) ? 1.0f / (float)d : 0.0f;
    ((float4*)(g_mean + (size_t)node * F))[lane] =
        make_float4(a0 * inv, a1 * inv, a2 * inv, a3 * inv);
}

// ---------------- HMMA GEMM: 2 CTAs/SM, W cp.async double-buffered --------------
#define SM_BIAS  0
#define SM_AHI   1024
#define SM_ALO   (SM_AHI + 16384)
#define SM_WHI0  (SM_ALO + 16384)
#define SM_WLO0  (SM_WHI0 + 16384)
#define SM_WHI1  (SM_WLO0 + 16384)
#define SM_WLO1  (SM_WHI1 + 16384)
#define SM_TOTAL (SM_WLO1 + 16384)   // 99328 bytes -> 2 CTAs/SM

__device__ __forceinline__ unsigned swoff(int row, int k) {
    return (unsigned)(row * 128 + ((((k >> 3) ^ row) & 7) << 4) + (k & 7) * 2);
}

__device__ __forceinline__ void issue_w(int chunk, unsigned sb, int tid,
                                        const __nv_bfloat16* Whi,
                                        const __nv_bfloat16* Wlo) {
    int kcW = chunk * 64;
    int buf = chunk & 1;
    unsigned whb = sb + (buf ? SM_WHI1 : SM_WHI0);
    unsigned wlb = sb + (buf ? SM_WLO1 : SM_WLO0);
#pragma unroll
    for (int q = 0; q < 4; q++) {
        int i = tid + q * 256;             // 0..1023
        int n = i >> 3;
        int k8 = (i & 7) * 8;
        unsigned off = swoff(n, k8);
        cp16(whb + off, Whi + n * 256 + kcW + k8);
        cp16(wlb + off, Wlo + n * 256 + kcW + k8);
    }
}

__global__ void __launch_bounds__(256, 2) k_gemm(
    const float* __restrict__ Am,
    const float* __restrict__ Ah,
    const __nv_bfloat16* __restrict__ Whi,
    const __nv_bfloat16* __restrict__ Wlo,
    const float* __restrict__ bl,
    float* __restrict__ outh)
{
    extern __shared__ __align__(16) char smem[];
    unsigned sb = smem_u32(smem);
    int tid = threadIdx.x;
    int wid = tid >> 5;
    int lane = tid & 31;
    int wm = wid & 1;
    int wn = wid >> 1;
    int m0 = blockIdx.x * 128;

    if (tid < 128) *(float*)(smem + SM_BIAS + tid * 4) = bl[tid];

    float acc[4][4][4];
#pragma unroll
    for (int a = 0; a < 4; a++)
#pragma unroll
        for (int b = 0; b < 4; b++)
#pragma unroll
            for (int c = 0; c < 4; c++) acc[a][b][c] = 0.f;

    issue_w(0, sb, tid, Whi, Wlo);
    CP_COMMIT();

    // A load indices for this thread (128 rows x 64 cols, 8 float4 each)
    int arow = tid >> 4;            // 0..15 base row group? -> i>>4 pattern
    for (int chunk = 0; chunk < 4; chunk++) {
        int buf = chunk & 1;
        const float* ap = (chunk < 2) ? Am : Ah;
        int kcA = (chunk & 1) * 64;

        // A: direct LDG into regs (latency overlapped by co-resident CTA)
        float4 av[8];
#pragma unroll
        for (int q = 0; q < 8; q++) {
            int i = tid + q * 256;
            int row = i >> 4;
            int k4 = (i & 15) * 4;
            int gr = m0 + row;
            av[q] = (gr < N_NODES) ? *(const float4*)(ap + (size_t)gr * F + kcA + k4)
                                   : make_float4(0.f, 0.f, 0.f, 0.f);
        }

        CP_WAIT0();             // W chunk landed
        __syncthreads();        // prev MMA done; A planes free
        if (chunk < 3) {
            issue_w(chunk + 1, sb, tid, Whi, Wlo);
            CP_COMMIT();
        }
        // split A regs -> hi/lo planes
#pragma unroll
        for (int q = 0; q < 8; q++) {
            int i = tid + q * 256;
            int row = i >> 4;
            int k4 = (i & 15) * 4;
            uint2 h, l;
            split2(av[q].x, av[q].y, h.x, l.x);
            split2(av[q].z, av[q].w, h.y, l.y);
            unsigned off = swoff(row, k4);
            *(uint2*)(smem + SM_AHI + off) = h;
            *(uint2*)(smem + SM_ALO + off) = l;
        }
        __syncthreads();

        unsigned whb = sb + (buf ? SM_WHI1 : SM_WHI0);
        unsigned wlb = sb + (buf ? SM_WLO1 : SM_WLO0);
#pragma unroll
        for (int ks = 0; ks < 4; ks++) {
            int kl = ks * 16;
            // B fragments first (16 regs live)
            unsigned bhi[8], blo[8];
            int nrl = (lane >> 4) * 8 + (lane & 7);
            int kkB = kl + ((lane >> 3) & 1) * 8;
#pragma unroll
            for (int nf2 = 0; nf2 < 2; nf2++) {
                int nrow = wn * 32 + nf2 * 16 + nrl;
                unsigned offB = (unsigned)(nrow * 128 + ((((kkB >> 3) ^ nrow) & 7) << 4));
                ldsm_x4(&bhi[nf2 * 4], whb + offB);
                ldsm_x4(&blo[nf2 * 4], wlb + offB);
            }
            int mrl = ((lane >> 3) & 1) * 8 + (lane & 7);
            int kkA = kl + (lane >> 4) * 8;
#pragma unroll
            for (int mf = 0; mf < 4; mf++) {
                unsigned ahi[4], alo[4];
                int mrow = wm * 64 + mf * 16 + mrl;
                unsigned offA = (unsigned)(mrow * 128 + ((((kkA >> 3) ^ mrow) & 7) << 4));
                ldsm_x4(ahi, sb + SM_AHI + offA);
                ldsm_x4(alo, sb + SM_ALO + offA);
#pragma unroll
                for (int nf = 0; nf < 4; nf++) {
                    const unsigned* bh = &bhi[(nf >> 1) * 4 + (nf & 1) * 2];
                    const unsigned* blp = &blo[(nf >> 1) * 4 + (nf & 1) * 2];
                    mma16816(acc[mf][nf], ahi, bh);
                    mma16816(acc[mf][nf], ahi, blp);
                    mma16816(acc[mf][nf], alo, bh);
                }
            }
        }
    }

    // epilogue: bias + relu, fp32 stores
    const float* bias = (const float*)(smem + SM_BIAS);
#pragma unroll
    for (int mf = 0; mf < 4; mf++) {
        int ra = m0 + wm * 64 + mf * 16 + (lane >> 2);
        int rb = ra + 8;
#pragma unroll
        for (int nf = 0; nf < 4; nf++) {
            int col = wn * 32 + nf * 8 + (lane & 3) * 2;
            float b0 = bias[col], b1 = bias[col + 1];
            if (ra < N_NODES) {
                float v0 = fmaxf(acc[mf][nf][0] + b0, 0.f);
                float v1 = fmaxf(acc[mf][nf][1] + b1, 0.f);
                *(float2*)(outh + (size_t)ra * F + col) = make_float2(v0, v1);
            }
            if (rb < N_NODES) {
                float v2 = fmaxf(acc[mf][nf][2] + b0, 0.f);
                float v3 = fmaxf(acc[mf][nf][3] + b1, 0.f);
                *(float2*)(outh + (size_t)rb * F + col) = make_float2(v2, v3);
            }
        }
    }
}

// ---------------- final linear + deg re-zero for next call ----------------------
__global__ void k_final(const float* __restrict__ h,
                        const float* __restrict__ Wf,
                        const float* __restrict__ bf,
                        float* __restrict__ out)
{
    int gid = blockIdx.x * blockDim.x + threadIdx.x;
    if (gid < N_NODES) g_deg[gid] = 0;        // prep for next call's histogram
    int node = gid >> 5;
    if (node >= N_NODES) return;
    int lane = gid & 31;
    float4 hv = ((const float4*)(h + (size_t)node * F))[lane];
    float4 wv = ((const float4*)Wf)[lane];
    float s = hv.x * wv.x + hv.y * wv.y + hv.z * wv.z + hv.w * wv.w;
#pragma unroll
    for (int o = 16; o > 0; o >>= 1) s += __shfl_down_sync(0xFFFFFFFFu, s, o);
    if (lane == 0) out[node] = s + bf[0];
}

// ---------------- launch ------------------------------------------------------------
extern "C" void kernel_launch(void* const* d_in, const int* in_sizes, int n_in,
                              void* d_out, int out_size)
{
    const float* x    = (const float*)d_in[0];
    const int*   edge = (const int*)d_in[1];   // int32 (JAX x64 disabled)
    const float* Wl[3] = {(const float*)d_in[2], (const float*)d_in[5], (const float*)d_in[8]};
    const float* bl[3] = {(const float*)d_in[3], (const float*)d_in[6], (const float*)d_in[9]};
    const float* Wr[3] = {(const float*)d_in[4], (const float*)d_in[7], (const float*)d_in[10]};
    const float* Wf = (const float*)d_in[11];
    const float* bf = (const float*)d_in[12];
    float* out = (float*)d_out;

    cudaFuncSetAttribute(k_gemm, cudaFuncAttributeMaxDynamicSharedMemorySize, SM_TOTAL);

    void* p = nullptr;
    cudaGetSymbolAddress(&p, g_h);
    float* h0 = (float*)p;
    float* h1 = h0 + (size_t)N_NODES * F;
    cudaGetSymbolAddress(&p, g_mean);
    float* mp = (float*)p;
    cudaGetSymbolAddress(&p, g_whi);
    __nv_bfloat16* whi = (__nv_bfloat16*)p;
    cudaGetSymbolAddress(&p, g_wlo);
    __nv_bfloat16* wlo = (__nv_bfloat16*)p;

    const int AGG_BLOCKS = (N_NODES * 32 + 255) / 256;
    const int GEMM_BLOCKS = (N_NODES + 127) / 128;   // 391

    // 0: prep (pack W + histogram + flag reset)
    k_prep<<<(N_EDGES / 4 + 255) / 256, 256>>>(edge, Wl[0], Wr[0], Wl[1], Wr[1], Wl[2], Wr[2]);
    // 1: fused scan + scatter
    k_scan_scatter<<<NBLK_SCAN, 256>>>(edge);

    // 2: agg0   3: gemm0 (ncu capture slot)
    k_agg<<<AGG_BLOCKS, 256>>>(x);
    k_gemm<<<GEMM_BLOCKS, 256, SM_TOTAL>>>(mp, x, whi, wlo, bl[0], h0);
    // 4,5: layer 1
    k_agg<<<AGG_BLOCKS, 256>>>(h0);
    k_gemm<<<GEMM_BLOCKS, 256, SM_TOTAL>>>(mp, h0, whi + 128 * 256, wlo + 128 * 256, bl[1], h1);
    // 6,7: layer 2
    k_agg<<<AGG_BLOCKS, 256>>>(h1);
    k_gemm<<<GEMM_BLOCKS, 256, SM_TOTAL>>>(mp, h1, whi + 2 * 128 * 256, wlo + 2 * 128 * 256, bl[2], h0);
    // 8: final (+ deg zero for next call)
    k_final<<<AGG_BLOCKS, 256>>>(h0, Wf, bf, out);
}